// round 14
// baseline (speedup 1.0000x reference)
#include <cuda_runtime.h>
#include <cuda_bf16.h>
#include <cuda_fp16.h>
#include <math.h>
#include <stdint.h>

#define BB 4
#define LL 2048
#define DMODEL 1024
#define DSTATE 16
#define DCONV 4
#define DINNER 2048
#define M_ROWS (BB*LL)            // 8192
#define NCH 16
#define CHL 128
#define KSPLIT 4

typedef unsigned int u32;
typedef unsigned long long u64;
typedef __nv_bfloat16 bf16;
typedef uint16_t u16;

// ---------------- scratch (device globals) ----------------
__device__ __align__(16) __half g_xzh[(size_t)M_ROWS * (2*DINNER)];
__device__ __align__(16) __half g_xh[(size_t)M_ROWS * DMODEL];
__device__ __align__(16) __half g_winT[(size_t)(2*DINNER) * DMODEL];
__device__ __align__(16) bf16  g_xch[(size_t)M_ROWS * DINNER];
__device__ __align__(16) bf16  g_xcl[(size_t)M_ROWS * DINNER];
__device__ __align__(16) bf16  g_wxT_h[64 * DINNER];
__device__ __align__(16) bf16  g_wxT_l[64 * DINNER];
__device__ __align__(16) float g_xdbl4[(size_t)KSPLIT * M_ROWS * 64];
__device__ __align__(16) float g_coef[(size_t)M_ROWS * 48];
__device__ __align__(16) float g_ptot[BB * NCH * DSTATE];
__device__ __align__(16) float g_hend[(size_t)BB * NCH * DINNER * DSTATE];
__device__ __align__(16) float g_hstart[(size_t)BB * NCH * DINNER * DSTATE];
__device__ __align__(16) __half g_yh[(size_t)M_ROWS * DINNER];
__device__ __align__(16) __half g_woutT[(size_t)DMODEL * DINNER];

// ---------------- PTX helpers (BASE PTX ONLY) ----------------
__device__ __forceinline__ u32 smem_u32(const void* p) {
    u32 a; asm("{ .reg .u64 t; cvta.to.shared.u64 t, %1; cvt.u32.u64 %0, t; }" : "=r"(a) : "l"(p));
    return a;
}
__device__ __forceinline__ void cp16(u32 dst, const void* src) {
    asm volatile("cp.async.cg.shared.global [%0], [%1], 16;" :: "r"(dst), "l"(src));
}
__device__ __forceinline__ void cp_commit() {
    asm volatile("cp.async.commit_group;" ::: "memory");
}
__device__ __forceinline__ void ldsm4(u32* r, u32 addr) {
    asm volatile("ldmatrix.sync.aligned.m8n8.x4.shared.b16 {%0,%1,%2,%3}, [%4];"
                 : "=r"(r[0]), "=r"(r[1]), "=r"(r[2]), "=r"(r[3]) : "r"(addr));
}
__device__ __forceinline__ void mma_bf16(float* d, const u32* a, const u32 b0, const u32 b1) {
    asm volatile(
        "mma.sync.aligned.m16n8k16.row.col.f32.bf16.bf16.f32 "
        "{%0,%1,%2,%3}, {%4,%5,%6,%7}, {%8,%9}, {%0,%1,%2,%3};"
        : "+f"(d[0]), "+f"(d[1]), "+f"(d[2]), "+f"(d[3])
        : "r"(a[0]), "r"(a[1]), "r"(a[2]), "r"(a[3]), "r"(b0), "r"(b1));
}
__device__ __forceinline__ void mma_f16(float* d, const u32* a, const u32 b0, const u32 b1) {
    asm volatile(
        "mma.sync.aligned.m16n8k16.row.col.f32.f16.f16.f32 "
        "{%0,%1,%2,%3}, {%4,%5,%6,%7}, {%8,%9}, {%0,%1,%2,%3};"
        : "+f"(d[0]), "+f"(d[1]), "+f"(d[2]), "+f"(d[3])
        : "r"(a[0]), "r"(a[1]), "r"(a[2]), "r"(a[3]), "r"(b0), "r"(b1));
}
__device__ __forceinline__ u64 pk2(float a, float b) {
    u64 r; asm("mov.b64 %0, {%1, %2};" : "=l"(r) : "f"(a), "f"(b)); return r;
}
__device__ __forceinline__ void up2(float& a, float& b, u64 v) {
    asm("mov.b64 {%0, %1}, %2;" : "=f"(a), "=f"(b) : "l"(v));
}
__device__ __forceinline__ u64 mul2(u64 a, u64 b) {
    u64 d; asm("mul.rn.f32x2 %0, %1, %2;" : "=l"(d) : "l"(a), "l"(b)); return d;
}
__device__ __forceinline__ u64 fma2(u64 a, u64 b, u64 c) {
    u64 d; asm("fma.rn.f32x2 %0, %1, %2, %3;" : "=l"(d) : "l"(a), "l"(b), "l"(c)); return d;
}

// ---------------- fp16 1-product HMMA GEMM body (R13 mainloop) ----------------
#define PITCH 144

template<typename OutT>
__device__ __forceinline__ void gemm_body(
    const u16* __restrict__ Ah, const u16* __restrict__ Bh,
    OutT* __restrict__ C, int N, int K, long brow, long bcol, char* smem)
{
    constexpr int ABYT = 128 * PITCH;
    constexpr int STAGE = 2 * ABYT;
    const u32 sb = smem_u32(smem);

    const int tid = threadIdx.x;
    const int wid  = tid >> 5;
    const int lane = tid & 31;
    const int wm = wid & 1;
    const int wn = wid >> 1;

    const int a_row  = lane & 15;
    const int a_colb = (lane >> 4) * 16;
    const int q = lane >> 3;
    const int b_n  = (lane & 7) + ((q >> 1) << 3);
    const int b_kb = (q & 1) * 16;

    const u32 aAddr = sb + (u32)((wm*64 + a_row) * PITCH + a_colb);
    const u32 bAddr = sb + ABYT + (u32)((wn*32 + b_n) * PITCH + b_kb);

    float acc[4][4][4];
    #pragma unroll
    for (int i = 0; i < 4; i++)
        #pragma unroll
        for (int j = 0; j < 4; j++)
            #pragma unroll
            for (int v = 0; v < 4; v++) acc[i][j][v] = 0.0f;

    const int nst = K >> 6;

    auto load_quarter = [&](int s, int qtr) {
        const u32 base = sb + (u32)((s % 3) * STAGE);
        const int kt = s << 6;
        int i = tid + qtr * 256;
        int r = i >> 3, ch = i & 7;
        u32 d = base + (u32)(r * PITCH + ch * 16);
        cp16(d, Ah + (brow + r) * (long)K + kt + ch * 8);
        cp16(d + ABYT, Bh + (bcol + r) * (long)K + kt + ch * 8);
    };
    auto load_stage = [&](int s) {
        #pragma unroll
        for (int qtr = 0; qtr < 4; qtr++) load_quarter(s, qtr);
        cp_commit();
    };

    load_stage(0);
    load_stage(1);

    u32 afr[2][4];
    u32 bfr[2][2][4];

    for (int s = 0; s < nst; s++) {
        if (s + 1 < nst) asm volatile("cp.async.wait_group 1;" ::: "memory");
        else             asm volatile("cp.async.wait_group 0;" ::: "memory");
        __syncthreads();

        const u32 boff = (u32)((s % 3) * STAGE);
        const bool more = (s + 2 < nst);

        ldsm4(bfr[0][0], bAddr + boff);
        ldsm4(bfr[0][1], bAddr + boff + 16*PITCH);
        ldsm4(afr[0],    aAddr + boff);

        #pragma unroll
        for (int kk = 0; kk < 4; kk++) {
            const int cb = kk & 1;
            const u32 kadd0 = kk * 32;
            if (more) load_quarter(s + 2, kk);
            if (kk == 3 && more) cp_commit();
            if (kk < 3) {
                const u32 kadd = (kk + 1) * 32;
                ldsm4(bfr[cb^1][0], bAddr + boff + kadd);
                ldsm4(bfr[cb^1][1], bAddr + boff + kadd + 16*PITCH);
            }
            #pragma unroll
            for (int mt = 0; mt < 4; mt++) {
                const int ca = (kk * 4 + mt) & 1;
                if (mt < 3)
                    ldsm4(afr[ca^1], aAddr + boff + kadd0 + (u32)((mt+1)*16*PITCH));
                else if (kk < 3)
                    ldsm4(afr[ca^1], aAddr + boff + (u32)((kk+1)*32));
                #pragma unroll
                for (int nt = 0; nt < 4; nt++) {
                    const int p = nt >> 1, h = nt & 1;
                    mma_f16(acc[mt][nt], afr[ca], bfr[cb][p][2*h], bfr[cb][p][2*h+1]);
                }
            }
        }
        if (!more) { if (s + 2 == nst) cp_commit(); }
    }

    #pragma unroll
    for (int mt = 0; mt < 4; mt++) {
        long r0 = brow + wm*64 + mt*16 + (lane >> 2);
        long cc = bcol + wn*32 + ((lane & 3) << 1);
        #pragma unroll
        for (int nt = 0; nt < 4; nt++) {
            if (sizeof(OutT) == 2) {
                __half2* p0 = (__half2*)((__half*)C + r0 * N + cc + nt*8);
                __half2* p1 = (__half2*)((__half*)C + (r0+8) * N + cc + nt*8);
                *p0 = __floats2half2_rn(acc[mt][nt][0], acc[mt][nt][1]);
                *p1 = __floats2half2_rn(acc[mt][nt][2], acc[mt][nt][3]);
            } else {
                float2 v0 = make_float2(acc[mt][nt][0], acc[mt][nt][1]);
                float2 v1 = make_float2(acc[mt][nt][2], acc[mt][nt][3]);
                *(float2*)((float*)C + r0 * N + cc + nt*8)     = v0;
                *(float2*)((float*)C + (r0+8) * N + cc + nt*8) = v1;
            }
        }
    }
}

template<typename OutT>
__global__ __launch_bounds__(256, 2) void gemm_f16(
    const u16* __restrict__ Ah, const u16* __restrict__ Bh,
    OutT* __restrict__ C, int N, int K, long row0)
{
    extern __shared__ __align__(16) char smem[];
    gemm_body<OutT>(Ah, Bh, C, N, K, row0 + (long)blockIdx.y * 128,
                    (long)blockIdx.x * 128, smem);
}

// ---------------- scan pass 3 body (2-wide) ----------------
__device__ __forceinline__ void pass3_body(
    const float* __restrict__ coef, const float* __restrict__ hstart,
    const bf16* __restrict__ xch, const bf16* __restrict__ xcl,
    const __half* __restrict__ xz, const float* __restrict__ Dp,
    __half* __restrict__ yh, int dblk, int c, int b, float* sc)
{
    int tid = threadIdx.x;
    int d0 = dblk * 512 + tid * 2;
    long lbase = (long)b * LL + c * CHL;
    for (int i = tid; i < CHL*48; i += 256)
        sc[i] = coef[lbase*48 + i];
    __syncthreads();

    u64 ha[8], hb[8];
    const u64* hsp = (const u64*)(hstart + (((long)(b*NCH + c) * DINNER) + d0) * 16);
    #pragma unroll
    for (int j = 0; j < 8; j++) { ha[j] = hsp[j]; hb[j] = hsp[8 + j]; }
    float Da = Dp[d0], Db = Dp[d0+1];

    for (int l = 0; l < CHL; l++) {
        long row = lbase + l;
        long ix = row*DINNER + d0;
        float2 fh = __bfloat1622float2(*(const __nv_bfloat162*)(xch + ix));
        float2 fl = __bfloat1622float2(*(const __nv_bfloat162*)(xcl + ix));
        float xa = fh.x + fl.x, xb = fh.y + fl.y;
        float2 zf = __half22float2(*(const __half2*)(xz + row*(2*DINNER) + DINNER + d0));
        u64 xxa = pk2(xa, xa), xxb = pk2(xb, xb);
        const u64* ap = (const u64*)sc + l*24;
        u64 ya = 0ull, yb = 0ull;
        #pragma unroll
        for (int j = 0; j < 8; j++) {
            ha[j] = fma2(ap[j], ha[j], mul2(ap[8+j], xxa));
            hb[j] = fma2(ap[j], hb[j], mul2(ap[8+j], xxb));
            ya = fma2(ha[j], ap[16+j], ya);
            yb = fma2(hb[j], ap[16+j], yb);
        }
        float a0, a1, b0, b1;
        up2(a0, a1, ya); up2(b0, b1, yb);
        float vy0 = a0 + a1 + xa * Da;
        float vy1 = b0 + b1 + xb * Db;
        float sg0 = zf.x / (1.0f + __expf(-zf.x));
        float sg1 = zf.y / (1.0f + __expf(-zf.y));
        *(__half2*)(yh + ix) = __floats2half2_rn(vy0 * sg0, vy1 * sg1);
    }
}

__global__ __launch_bounds__(256) void scan_pass3(
    const float* __restrict__ coef, const float* __restrict__ hstart,
    const bf16* __restrict__ xch, const bf16* __restrict__ xcl,
    const __half* __restrict__ xz, const float* __restrict__ Dp,
    __half* __restrict__ yh, int b0)
{
    __shared__ float sc[CHL*48];
    pass3_body(coef, hstart, xch, xcl, xz, Dp, yh,
               blockIdx.x, blockIdx.y, blockIdx.z + b0, sc);
}

// ---------------- FUSED: p3(batches 2,3) + GEMM2(rows 0..4095) ----------------
// blockIdx.x in [0,128): p3 CTA; [128,384): GEMM2 M-tiles 0..31 x N-tiles 0..7.
__global__ __launch_bounds__(256, 2) void p3_g2_fused(
    const float* __restrict__ coef, const float* __restrict__ hstart,
    const bf16* __restrict__ xch, const bf16* __restrict__ xcl,
    const __half* __restrict__ xz, const float* __restrict__ Dp,
    __half* __restrict__ yh,
    const u16* __restrict__ woutT, float* __restrict__ out)
{
    extern __shared__ __align__(16) char smem[];
    int id = blockIdx.x;
    if (id < 128) {
        pass3_body(coef, hstart, xch, xcl, xz, Dp, yh,
                   id & 3, (id >> 2) & 15, 2 + (id >> 6), (float*)smem);
    } else {
        id -= 128;
        gemm_body<float>((const u16*)yh, woutT, out, 1024, 2048,
                         (long)(id >> 3) * 128, (long)(id & 7) * 128, smem);
    }
}

// ---------------- wx GEMM: 64x64 tile, bf16 3-product, SPLIT-K x4 ----------------
#define WPITCH 80

__global__ __launch_bounds__(256, 3) void gemm_wx64(
    const u16* __restrict__ Ah, const u16* __restrict__ Al,
    const u16* __restrict__ Bh, const u16* __restrict__ Bl,
    float* __restrict__ Cpart, int N, int K)
{
    constexpr int ABYT = 64 * WPITCH;
    constexpr int OFF_AL = ABYT;
    constexpr int OFF_BH = 2 * ABYT;
    constexpr int OFF_BL = 3 * ABYT;
    constexpr int STAGE = 4 * ABYT;

    extern __shared__ __align__(16) char smem[];
    const u32 sb = smem_u32(smem);

    const int tid = threadIdx.x;
    const int kp  = blockIdx.x;
    const long brow = (long)blockIdx.y * 64;
    const int kbase = kp * (K / KSPLIT);
    float* C = Cpart + (size_t)kp * M_ROWS * 64;

    const int wid  = tid >> 5;
    const int lane = tid & 31;
    const int wm = wid & 1;
    const int wn = wid >> 1;

    const int a_row  = lane & 15;
    const int a_colb = (lane >> 4) * 16;
    const int q = lane >> 3;
    const int b_n  = (lane & 7) + ((q >> 1) << 3);
    const int b_kb = (q & 1) * 16;

    const u32 aAddrH = sb + (u32)((wm*32 + a_row) * WPITCH + a_colb);
    const u32 aAddrL = aAddrH + OFF_AL;
    const u32 bAddrH = sb + OFF_BH + (u32)((wn*16 + b_n) * WPITCH + b_kb);
    const u32 bAddrL = bAddrH + ABYT;

    float acc[2][2][4];
    #pragma unroll
    for (int i = 0; i < 2; i++)
        #pragma unroll
        for (int j = 0; j < 2; j++)
            #pragma unroll
            for (int v = 0; v < 4; v++) acc[i][j][v] = 0.0f;

    const int nst = (K / KSPLIT) >> 5;

    auto load_stage = [&](int s) {
        const u32 base = sb + (u32)((s % 3) * STAGE);
        const int kt = kbase + (s << 5);
        {
            int i = tid;
            int r = i >> 2, ch = i & 3;
            u32 d = base + (u32)(r * WPITCH + ch * 16);
            long g = (brow + r) * (long)K + kt + ch * 8;
            cp16(d, Ah + g);
            cp16(d + OFF_AL, Al + g);
            long gb = (long)r * K + kt + ch * 8;
            cp16(d + OFF_BH, Bh + gb);
            cp16(d + OFF_BL, Bl + gb);
        }
        cp_commit();
    };

    load_stage(0);
    load_stage(1);

    for (int s = 0; s < nst; s++) {
        if (s + 1 < nst) asm volatile("cp.async.wait_group 1;" ::: "memory");
        else             asm volatile("cp.async.wait_group 0;" ::: "memory");
        __syncthreads();
        if (s + 2 < nst) load_stage(s + 2);

        const u32 boff = (u32)((s % 3) * STAGE);
        #pragma unroll
        for (int kk = 0; kk < 2; kk++) {
            const u32 kadd = kk * 32;
            u32 bh[4], bl[4];
            ldsm4(bh, bAddrH + boff + kadd);
            ldsm4(bl, bAddrL + boff + kadd);
            #pragma unroll
            for (int mt = 0; mt < 2; mt++) {
                u32 ah[4], al[4];
                ldsm4(ah, aAddrH + boff + kadd + (u32)(mt*16*WPITCH));
                ldsm4(al, aAddrL + boff + kadd + (u32)(mt*16*WPITCH));
                #pragma unroll
                for (int nt = 0; nt < 2; nt++) {
                    mma_bf16(acc[mt][nt], ah, bh[2*nt], bh[2*nt+1]);
                    mma_bf16(acc[mt][nt], ah, bl[2*nt], bl[2*nt+1]);
                    mma_bf16(acc[mt][nt], al, bh[2*nt], bh[2*nt+1]);
                }
            }
        }
    }

    #pragma unroll
    for (int mt = 0; mt < 2; mt++) {
        long r0 = brow + wm*32 + mt*16 + (lane >> 2);
        long cc = wn*16 + ((lane & 3) << 1);
        #pragma unroll
        for (int nt = 0; nt < 2; nt++) {
            float2 v0 = make_float2(acc[mt][nt][0], acc[mt][nt][1]);
            float2 v1 = make_float2(acc[mt][nt][2], acc[mt][nt][3]);
            *(float2*)&C[r0 * N + cc + nt*8]     = v0;
            *(float2*)&C[(r0+8) * N + cc + nt*8] = v1;
        }
    }
}

// ---------------- fused operand prep ----------------
__global__ void prep_fused(
    const float* __restrict__ x, __half* __restrict__ xh,
    const float* __restrict__ W_in, __half* __restrict__ winT,
    const float* __restrict__ W_out, __half* __restrict__ woutT,
    const float* __restrict__ W_x, bf16* __restrict__ wxh, bf16* __restrict__ wxl)
{
    int bi = blockIdx.x;
    const int tx = threadIdx.x, ty = threadIdx.y;
    if (bi < 32768) {
        int i = bi * 256 + ty * 32 + tx;
        xh[i] = __float2half_rn(x[i]);
        return;
    }
    bi -= 32768;
    __shared__ float t[32][33];
    if (bi < 4096) {
        const int R = 1024, Cc = 4096;
        int c0 = (bi & 127) * 32, r0 = (bi >> 7) * 32;
        #pragma unroll
        for (int i = 0; i < 32; i += 8)
            t[ty + i][tx] = W_in[(long)(r0 + ty + i) * Cc + c0 + tx];
        __syncthreads();
        #pragma unroll
        for (int i = 0; i < 32; i += 8)
            winT[(long)(c0 + ty + i) * R + r0 + tx] = __float2half_rn(t[tx][ty + i]);
        return;
    }
    bi -= 4096;
    if (bi < 2048) {
        const int R = 2048, Cc = 1024;
        int c0 = (bi & 31) * 32, r0 = (bi >> 5) * 32;
        #pragma unroll
        for (int i = 0; i < 32; i += 8)
            t[ty + i][tx] = W_out[(long)(r0 + ty + i) * Cc + c0 + tx];
        __syncthreads();
        #pragma unroll
        for (int i = 0; i < 32; i += 8)
            woutT[(long)(c0 + ty + i) * R + r0 + tx] = __float2half_rn(t[tx][ty + i]);
        return;
    }
    bi -= 2048;
    {
        const int R = 2048, Cc = 33;
        int c0 = (bi & 1) * 32, r0 = (bi >> 1) * 32;
        #pragma unroll
        for (int i = 0; i < 32; i += 8) {
            int c = c0 + tx;
            t[ty + i][tx] = (c < Cc) ? W_x[(long)(r0 + ty + i) * Cc + c] : 0.0f;
        }
        __syncthreads();
        #pragma unroll
        for (int i = 0; i < 32; i += 8) {
            int oc = c0 + ty + i;
            float v = t[tx][ty + i];
            bf16 h = __float2bfloat16_rn(v);
            wxh[(long)oc * R + r0 + tx] = h;
            wxl[(long)oc * R + r0 + tx] = __float2bfloat16_rn(v - __bfloat162float(h));
        }
    }
}

// ---------------- tiled depthwise causal conv (K=4) + SiLU, 2-wide ----------------
#define CONV_TL 32
__global__ __launch_bounds__(256) void conv_silu_tiled(
    const __half* __restrict__ xz, const float* __restrict__ conv_w,
    const float* __restrict__ conv_b,
    bf16* __restrict__ xch, bf16* __restrict__ xcl)
{
    __shared__ __half2 sx[CONV_TL + 3][256];
    const int tid = threadIdx.x;
    const int d0 = blockIdx.x * 512 + tid * 2;
    const int l0 = blockIdx.y * CONV_TL;
    const int b  = blockIdx.z;

    #pragma unroll 5
    for (int r = 0; r < CONV_TL + 3; r++) {
        int l = l0 - 3 + r;
        sx[r][tid] = (l >= 0) ? *(const __half2*)(xz + ((long)(b * LL + l)) * (2*DINNER) + d0)
                              : __half2(__float2half(0.f), __float2half(0.f));
    }
    __syncthreads();

    const float4 w0 = *(const float4*)&conv_w[d0 * DCONV];
    const float4 w1 = *(const float4*)&conv_w[(d0+1) * DCONV];
    const float bias0 = conv_b[d0];
    const float bias1 = conv_b[d0+1];

    #pragma unroll 4
    for (int j = 0; j < CONV_TL; j++) {
        float2 t0 = __half22float2(sx[j+0][tid]);
        float2 t1 = __half22float2(sx[j+1][tid]);
        float2 t2 = __half22float2(sx[j+2][tid]);
        float2 t3 = __half22float2(sx[j+3][tid]);
        float a0 = bias0 + t0.x*w0.x + t1.x*w0.y + t2.x*w0.z + t3.x*w0.w;
        float a1 = bias1 + t0.y*w1.x + t1.y*w1.y + t2.y*w1.z + t3.y*w1.w;
        float s0 = a0 / (1.0f + __expf(-a0));
        float s1 = a1 / (1.0f + __expf(-a1));
        long idx = ((long)(b * LL + l0 + j)) * DINNER + d0;
        bf16 h0 = __float2bfloat16_rn(s0);
        bf16 h1 = __float2bfloat16_rn(s1);
        bf16 l0v = __float2bfloat16_rn(s0 - __bfloat162float(h0));
        bf16 l1v = __float2bfloat16_rn(s1 - __bfloat162float(h1));
        *(__nv_bfloat162*)(xch + idx) = __nv_bfloat162(h0, h1);
        *(__nv_bfloat162*)(xcl + idx) = __nv_bfloat162(l0v, l1v);
    }
}

// ---------------- coefficients + chunk products, fused split-K reduce ----------------
__global__ __launch_bounds__(256) void coef_ptot(
    const float* __restrict__ xdbl4, const float* __restrict__ A_log,
    float* __restrict__ coef, float* __restrict__ ptot)
{
    const size_t PSZ = (size_t)M_ROWS * 64;
    __shared__ float sa[CHL][16];
    const int c = blockIdx.x, b = blockIdx.y, tid = threadIdx.x;
    const int n = tid & 15;
    const long lbase = (long)b * LL + c * CHL;
    const float Aneg = -expf(A_log[n]);

    for (int r0 = 0; r0 < CHL; r0 += 16) {
        int rloc = r0 + (tid >> 4);
        long r = lbase + rloc;
        const float* xr = xdbl4 + r * 64;
        float v  = ((xr[0]    + xr[PSZ])      + (xr[2*PSZ]      + xr[3*PSZ]));
        float bb = ((xr[1+n]  + xr[PSZ+1+n])  + (xr[2*PSZ+1+n]  + xr[3*PSZ+1+n]));
        float cc = ((xr[17+n] + xr[PSZ+17+n]) + (xr[2*PSZ+17+n] + xr[3*PSZ+17+n]));
        float delta = (v > 20.0f) ? v : log1pf(expf(v));
        float abar = expf(delta * Aneg);
        float* o = coef + r * 48;
        o[n]      = abar;
        o[16 + n] = delta * bb;
        o[32 + n] = cc;
        sa[rloc][n] = abar;
    }
    __syncthreads();
    if (tid < 16) {
        float p = 1.0f;
        #pragma unroll 8
        for (int l = 0; l < CHL; l++) p *= sa[l][tid];
        ptot[(b*NCH + c)*16 + tid] = p;
    }
}

// ---------------- scan pass 1: 2-wide ----------------
__global__ __launch_bounds__(256) void scan_pass1(
    const float* __restrict__ coef, const bf16* __restrict__ xch,
    const bf16* __restrict__ xcl, float* __restrict__ hend)
{
    __shared__ float sca[CHL*32];
    int b = blockIdx.z, c = blockIdx.y, tid = threadIdx.x;
    int d0 = blockIdx.x * 512 + tid * 2;
    long lbase = (long)b * LL + c * CHL;
    for (int i = tid; i < CHL*32; i += 256) {
        int row = i >> 5, j = i & 31;
        sca[i] = coef[(lbase + row)*48 + j];
    }
    __syncthreads();
    u64 ha[8], hb[8];
    #pragma unroll
    for (int j = 0; j < 8; j++) { ha[j] = 0ull; hb[j] = 0ull; }
    for (int l = 0; l < CHL; l++) {
        long ix = (lbase + l)*DINNER + d0;
        float2 fh = __bfloat1622float2(*(const __nv_bfloat162*)(xch + ix));
        float2 fl = __bfloat1622float2(*(const __nv_bfloat162*)(xcl + ix));
        float xa = fh.x + fl.x, xb = fh.y + fl.y;
        u64 xxa = pk2(xa, xa), xxb = pk2(xb, xb);
        const u64* ap = (const u64*)&sca[l*32];
        #pragma unroll
        for (int j = 0; j < 8; j++) {
            ha[j] = fma2(ap[j], ha[j], mul2(ap[8+j], xxa));
            hb[j] = fma2(ap[j], hb[j], mul2(ap[8+j], xxb));
        }
    }
    float* o = hend + (((long)(b*NCH + c) * DINNER) + d0) * 16;
    #pragma unroll
    for (int j = 0; j < 8; j++) {
        float x0, x1; up2(x0, x1, ha[j]);
        o[2*j] = x0; o[2*j+1] = x1;
    }
    #pragma unroll
    for (int j = 0; j < 8; j++) {
        float x0, x1; up2(x0, x1, hb[j]);
        o[16 + 2*j] = x0; o[16 + 2*j+1] = x1;
    }
}

// ---------------- scan pass 2 ----------------
__global__ __launch_bounds__(256) void scan_pass2(
    const float* __restrict__ hend, const float* __restrict__ ptot,
    float* __restrict__ hstart)
{
    long idx = (long)blockIdx.x * 256 + threadIdx.x;
    int n = (int)(idx & 15);
    int d = (int)((idx >> 4) & (DINNER-1));
    int b = (int)(idx >> 15);
    float hs = 0.0f;
    for (int c = 0; c < NCH; c++) {
        long o = (((long)(b*NCH + c) * DINNER) + d) * 16 + n;
        hstart[o] = hs;
        hs = ptot[(b*NCH + c)*16 + n] * hs + hend[o];
    }
}

// ---------------- launch ----------------
extern "C" void kernel_launch(void* const* d_in, const int* in_sizes, int n_in,
                              void* d_out, int out_size)
{
    const float* x       = (const float*)d_in[0];
    const float* W_in    = (const float*)d_in[1];
    const float* conv_w  = (const float*)d_in[2];
    const float* conv_b  = (const float*)d_in[3];
    const float* W_x     = (const float*)d_in[4];
    const float* A_log   = (const float*)d_in[5];
    const float* D_param = (const float*)d_in[6];
    const float* W_out   = (const float*)d_in[7];
    float* out = (float*)d_out;

    float *coefp, *xdbl4, *ptot, *hend, *hstart;
    __half *xzh, *xh, *winT, *woutT, *yh;
    bf16 *xch, *xcl, *wxh, *wxl;
    cudaGetSymbolAddress((void**)&xzh,   g_xzh);
    cudaGetSymbolAddress((void**)&coefp, g_coef);
    cudaGetSymbolAddress((void**)&xdbl4, g_xdbl4);
    cudaGetSymbolAddress((void**)&ptot,  g_ptot);
    cudaGetSymbolAddress((void**)&hend,  g_hend);
    cudaGetSymbolAddress((void**)&hstart,g_hstart);
    cudaGetSymbolAddress((void**)&xh,    g_xh);
    cudaGetSymbolAddress((void**)&winT,  g_winT);
    cudaGetSymbolAddress((void**)&woutT, g_woutT);
    cudaGetSymbolAddress((void**)&xch,   g_xch);
    cudaGetSymbolAddress((void**)&xcl,   g_xcl);
    cudaGetSymbolAddress((void**)&wxh,   g_wxT_h);
    cudaGetSymbolAddress((void**)&wxl,   g_wxT_l);
    cudaGetSymbolAddress((void**)&yh,    g_yh);

    const int SMEM1 = 3 * (2*128*PITCH);         // 110592
    const int SMEMW = 3 * (4*64*WPITCH);         // 61440
    cudaFuncSetAttribute((const void*)gemm_f16<__half>, cudaFuncAttributeMaxDynamicSharedMemorySize, SMEM1);
    cudaFuncSetAttribute((const void*)gemm_f16<float>,  cudaFuncAttributeMaxDynamicSharedMemorySize, SMEM1);
    cudaFuncSetAttribute((const void*)p3_g2_fused,      cudaFuncAttributeMaxDynamicSharedMemorySize, SMEM1);
    cudaFuncSetAttribute((const void*)gemm_wx64,        cudaFuncAttributeMaxDynamicSharedMemorySize, SMEMW);

    // 1) fused operand prep
    prep_fused<<<32768 + 4096 + 2048 + 128, dim3(32,8)>>>(
        x, xh, W_in, winT, W_out, woutT, W_x, wxh, wxl);
    // 2) GEMM1: xz(fp16) = x @ W_in
    gemm_f16<__half><<<dim3(4096/128, 8192/128), 256, SMEM1>>>(
        (const u16*)xh, (const u16*)winT, xzh, 4096, 1024, 0);
    // 3) conv + silu (2-wide)
    conv_silu_tiled<<<dim3(DINNER/512, LL/CONV_TL, BB), 256>>>(
        xzh, conv_w, conv_b, xch, xcl);
    // 4) x_dbl partials = xc @ W_x  (split-K x4)
    gemm_wx64<<<dim3(KSPLIT, 8192/64), 256, SMEMW>>>(
        (const u16*)xch, (const u16*)xcl, (const u16*)wxh, (const u16*)wxl, xdbl4, 64, 2048);
    // 5) coefficients + chunk products
    coef_ptot<<<dim3(NCH, BB), 256>>>(xdbl4, A_log, coefp, ptot);
    // 6-7) scan passes 1 & 2
    scan_pass1<<<dim3(DINNER/512, NCH, BB), 256>>>(coefp, xch, xcl, hend);
    scan_pass2<<<(BB*DINNER*DSTATE)/256, 256>>>(hend, ptot, hstart);
    // 8) scan pass 3, batches 0-1
    scan_pass3<<<dim3(DINNER/512, NCH, 2), 256>>>(coefp, hstart, xch, xcl, xzh, D_param, yh, 0);
    // 9) FUSED: pass 3 batches 2-3  ||  GEMM2 rows 0..4095
    p3_g2_fused<<<128 + 256, 256, SMEM1>>>(
        coefp, hstart, xch, xcl, xzh, D_param, yh, (const u16*)woutT, out);
    // 10) GEMM2 rows 4096..8191
    gemm_f16<float><<<dim3(1024/128, 4096/128), 256, SMEM1>>>(
        (const u16*)yh, (const u16*)woutT, out, 1024, 2048, 4096);
}

// round 15
// speedup vs baseline: 1.1153x; 1.1153x over previous
#include <cuda_runtime.h>
#include <cuda_bf16.h>
#include <cuda_fp16.h>
#include <math.h>
#include <stdint.h>

#define BB 4
#define LL 2048
#define DMODEL 1024
#define DSTATE 16
#define DCONV 4
#define DINNER 2048
#define M_ROWS (BB*LL)            // 8192
#define NCH 16
#define CHL 128
#define KSPLIT 4

typedef unsigned int u32;
typedef unsigned long long u64;
typedef __nv_bfloat16 bf16;
typedef uint16_t u16;

// ---------------- scratch (device globals) ----------------
__device__ __align__(16) __half g_xzh[(size_t)M_ROWS * (2*DINNER)];
__device__ __align__(16) __half g_xh[(size_t)M_ROWS * DMODEL];
__device__ __align__(16) __half g_winT[(size_t)(2*DINNER) * DMODEL];
__device__ __align__(16) bf16  g_xch[(size_t)M_ROWS * DINNER];
__device__ __align__(16) bf16  g_xcl[(size_t)M_ROWS * DINNER];
__device__ __align__(16) bf16  g_wxT_h[64 * DINNER];
__device__ __align__(16) bf16  g_wxT_l[64 * DINNER];
__device__ __align__(16) float g_xdbl4[(size_t)KSPLIT * M_ROWS * 64];
__device__ __align__(16) float g_coef[(size_t)M_ROWS * 48];
__device__ __align__(16) float g_ptot[BB * NCH * DSTATE];
__device__ __align__(16) float g_hend[(size_t)BB * NCH * DINNER * DSTATE];
__device__ __align__(16) float g_hstart[(size_t)BB * NCH * DINNER * DSTATE];
__device__ __align__(16) __half g_yh[(size_t)M_ROWS * DINNER];
__device__ __align__(16) __half g_woutT[(size_t)DMODEL * DINNER];

// ---------------- PTX helpers (BASE PTX ONLY) ----------------
__device__ __forceinline__ u32 smem_u32(const void* p) {
    u32 a; asm("{ .reg .u64 t; cvta.to.shared.u64 t, %1; cvt.u32.u64 %0, t; }" : "=r"(a) : "l"(p));
    return a;
}
__device__ __forceinline__ void cp16(u32 dst, const void* src) {
    asm volatile("cp.async.cg.shared.global [%0], [%1], 16;" :: "r"(dst), "l"(src));
}
__device__ __forceinline__ void cp_commit() {
    asm volatile("cp.async.commit_group;" ::: "memory");
}
__device__ __forceinline__ void ldsm4(u32* r, u32 addr) {
    asm volatile("ldmatrix.sync.aligned.m8n8.x4.shared.b16 {%0,%1,%2,%3}, [%4];"
                 : "=r"(r[0]), "=r"(r[1]), "=r"(r[2]), "=r"(r[3]) : "r"(addr));
}
__device__ __forceinline__ void mma_bf16(float* d, const u32* a, const u32 b0, const u32 b1) {
    asm volatile(
        "mma.sync.aligned.m16n8k16.row.col.f32.bf16.bf16.f32 "
        "{%0,%1,%2,%3}, {%4,%5,%6,%7}, {%8,%9}, {%0,%1,%2,%3};"
        : "+f"(d[0]), "+f"(d[1]), "+f"(d[2]), "+f"(d[3])
        : "r"(a[0]), "r"(a[1]), "r"(a[2]), "r"(a[3]), "r"(b0), "r"(b1));
}
__device__ __forceinline__ void mma_f16(float* d, const u32* a, const u32 b0, const u32 b1) {
    asm volatile(
        "mma.sync.aligned.m16n8k16.row.col.f32.f16.f16.f32 "
        "{%0,%1,%2,%3}, {%4,%5,%6,%7}, {%8,%9}, {%0,%1,%2,%3};"
        : "+f"(d[0]), "+f"(d[1]), "+f"(d[2]), "+f"(d[3])
        : "r"(a[0]), "r"(a[1]), "r"(a[2]), "r"(a[3]), "r"(b0), "r"(b1));
}
__device__ __forceinline__ u64 pk2(float a, float b) {
    u64 r; asm("mov.b64 %0, {%1, %2};" : "=l"(r) : "f"(a), "f"(b)); return r;
}
__device__ __forceinline__ void up2(float& a, float& b, u64 v) {
    asm("mov.b64 {%0, %1}, %2;" : "=f"(a), "=f"(b) : "l"(v));
}
__device__ __forceinline__ u64 mul2(u64 a, u64 b) {
    u64 d; asm("mul.rn.f32x2 %0, %1, %2;" : "=l"(d) : "l"(a), "l"(b)); return d;
}
__device__ __forceinline__ u64 fma2(u64 a, u64 b, u64 c) {
    u64 d; asm("fma.rn.f32x2 %0, %1, %2, %3;" : "=l"(d) : "l"(a), "l"(b), "l"(c)); return d;
}

// ---------------- fp16 1-product HMMA GEMM, cp.async spread across kk ----------------
#define PITCH 144

template<typename OutT>
__global__ __launch_bounds__(256, 2) void gemm_f16(
    const u16* __restrict__ Ah, const u16* __restrict__ Bh,
    OutT* __restrict__ C, int N, int K)
{
    constexpr int ABYT = 128 * PITCH;
    constexpr int STAGE = 2 * ABYT;

    extern __shared__ __align__(16) char smem[];
    const u32 sb = smem_u32(smem);

    const int tid = threadIdx.x;
    const long brow = (long)blockIdx.y * 128;
    const long bcol = (long)blockIdx.x * 128;

    const int wid  = tid >> 5;
    const int lane = tid & 31;
    const int wm = wid & 1;
    const int wn = wid >> 1;

    const int a_row  = lane & 15;
    const int a_colb = (lane >> 4) * 16;
    const int q = lane >> 3;
    const int b_n  = (lane & 7) + ((q >> 1) << 3);
    const int b_kb = (q & 1) * 16;

    const u32 aAddr = sb + (u32)((wm*64 + a_row) * PITCH + a_colb);
    const u32 bAddr = sb + ABYT + (u32)((wn*32 + b_n) * PITCH + b_kb);

    float acc[4][4][4];
    #pragma unroll
    for (int i = 0; i < 4; i++)
        #pragma unroll
        for (int j = 0; j < 4; j++)
            #pragma unroll
            for (int v = 0; v < 4; v++) acc[i][j][v] = 0.0f;

    const int nst = K >> 6;

    auto load_quarter = [&](int s, int qtr) {
        const u32 base = sb + (u32)((s % 3) * STAGE);
        const int kt = s << 6;
        int i = tid + qtr * 256;
        int r = i >> 3, ch = i & 7;
        u32 d = base + (u32)(r * PITCH + ch * 16);
        cp16(d, Ah + (brow + r) * (long)K + kt + ch * 8);
        cp16(d + ABYT, Bh + (bcol + r) * (long)K + kt + ch * 8);
    };
    auto load_stage = [&](int s) {
        #pragma unroll
        for (int qtr = 0; qtr < 4; qtr++) load_quarter(s, qtr);
        cp_commit();
    };

    load_stage(0);
    load_stage(1);

    u32 afr[2][4];
    u32 bfr[2][2][4];

    for (int s = 0; s < nst; s++) {
        if (s + 1 < nst) asm volatile("cp.async.wait_group 1;" ::: "memory");
        else             asm volatile("cp.async.wait_group 0;" ::: "memory");
        __syncthreads();

        const u32 boff = (u32)((s % 3) * STAGE);
        const bool more = (s + 2 < nst);

        ldsm4(bfr[0][0], bAddr + boff);
        ldsm4(bfr[0][1], bAddr + boff + 16*PITCH);
        ldsm4(afr[0],    aAddr + boff);

        #pragma unroll
        for (int kk = 0; kk < 4; kk++) {
            const int cb = kk & 1;
            const u32 kadd0 = kk * 32;
            if (more) load_quarter(s + 2, kk);
            if (kk == 3 && more) cp_commit();
            if (kk < 3) {
                const u32 kadd = (kk + 1) * 32;
                ldsm4(bfr[cb^1][0], bAddr + boff + kadd);
                ldsm4(bfr[cb^1][1], bAddr + boff + kadd + 16*PITCH);
            }
            #pragma unroll
            for (int mt = 0; mt < 4; mt++) {
                const int ca = (kk * 4 + mt) & 1;
                if (mt < 3)
                    ldsm4(afr[ca^1], aAddr + boff + kadd0 + (u32)((mt+1)*16*PITCH));
                else if (kk < 3)
                    ldsm4(afr[ca^1], aAddr + boff + (u32)((kk+1)*32));
                #pragma unroll
                for (int nt = 0; nt < 4; nt++) {
                    const int p = nt >> 1, h = nt & 1;
                    mma_f16(acc[mt][nt], afr[ca], bfr[cb][p][2*h], bfr[cb][p][2*h+1]);
                }
            }
        }
        if (!more) { if (s + 2 == nst) cp_commit(); }
    }

    #pragma unroll
    for (int mt = 0; mt < 4; mt++) {
        long r0 = brow + wm*64 + mt*16 + (lane >> 2);
        long cc = bcol + wn*32 + ((lane & 3) << 1);
        #pragma unroll
        for (int nt = 0; nt < 4; nt++) {
            if (sizeof(OutT) == 2) {
                __half2* p0 = (__half2*)((__half*)C + r0 * N + cc + nt*8);
                __half2* p1 = (__half2*)((__half*)C + (r0+8) * N + cc + nt*8);
                *p0 = __floats2half2_rn(acc[mt][nt][0], acc[mt][nt][1]);
                *p1 = __floats2half2_rn(acc[mt][nt][2], acc[mt][nt][3]);
            } else {
                float2 v0 = make_float2(acc[mt][nt][0], acc[mt][nt][1]);
                float2 v1 = make_float2(acc[mt][nt][2], acc[mt][nt][3]);
                *(float2*)((float*)C + r0 * N + cc + nt*8)     = v0;
                *(float2*)((float*)C + (r0+8) * N + cc + nt*8) = v1;
            }
        }
    }
}

// ---------------- wx GEMM: 64x64 tile, bf16 3-product, SPLIT-K x4 ----------------
#define WPITCH 80

__global__ __launch_bounds__(256, 3) void gemm_wx64(
    const u16* __restrict__ Ah, const u16* __restrict__ Al,
    const u16* __restrict__ Bh, const u16* __restrict__ Bl,
    float* __restrict__ Cpart, int N, int K)
{
    constexpr int ABYT = 64 * WPITCH;
    constexpr int OFF_AL = ABYT;
    constexpr int OFF_BH = 2 * ABYT;
    constexpr int OFF_BL = 3 * ABYT;
    constexpr int STAGE = 4 * ABYT;

    extern __shared__ __align__(16) char smem[];
    const u32 sb = smem_u32(smem);

    const int tid = threadIdx.x;
    const int kp  = blockIdx.x;
    const long brow = (long)blockIdx.y * 64;
    const int kbase = kp * (K / KSPLIT);
    float* C = Cpart + (size_t)kp * M_ROWS * 64;

    const int wid  = tid >> 5;
    const int lane = tid & 31;
    const int wm = wid & 1;
    const int wn = wid >> 1;

    const int a_row  = lane & 15;
    const int a_colb = (lane >> 4) * 16;
    const int q = lane >> 3;
    const int b_n  = (lane & 7) + ((q >> 1) << 3);
    const int b_kb = (q & 1) * 16;

    const u32 aAddrH = sb + (u32)((wm*32 + a_row) * WPITCH + a_colb);
    const u32 aAddrL = aAddrH + OFF_AL;
    const u32 bAddrH = sb + OFF_BH + (u32)((wn*16 + b_n) * WPITCH + b_kb);
    const u32 bAddrL = bAddrH + ABYT;

    float acc[2][2][4];
    #pragma unroll
    for (int i = 0; i < 2; i++)
        #pragma unroll
        for (int j = 0; j < 2; j++)
            #pragma unroll
            for (int v = 0; v < 4; v++) acc[i][j][v] = 0.0f;

    const int nst = (K / KSPLIT) >> 5;

    auto load_stage = [&](int s) {
        const u32 base = sb + (u32)((s % 3) * STAGE);
        const int kt = kbase + (s << 5);
        {
            int i = tid;
            int r = i >> 2, ch = i & 3;
            u32 d = base + (u32)(r * WPITCH + ch * 16);
            long g = (brow + r) * (long)K + kt + ch * 8;
            cp16(d, Ah + g);
            cp16(d + OFF_AL, Al + g);
            long gb = (long)r * K + kt + ch * 8;
            cp16(d + OFF_BH, Bh + gb);
            cp16(d + OFF_BL, Bl + gb);
        }
        cp_commit();
    };

    load_stage(0);
    load_stage(1);

    for (int s = 0; s < nst; s++) {
        if (s + 1 < nst) asm volatile("cp.async.wait_group 1;" ::: "memory");
        else             asm volatile("cp.async.wait_group 0;" ::: "memory");
        __syncthreads();
        if (s + 2 < nst) load_stage(s + 2);

        const u32 boff = (u32)((s % 3) * STAGE);
        #pragma unroll
        for (int kk = 0; kk < 2; kk++) {
            const u32 kadd = kk * 32;
            u32 bh[4], bl[4];
            ldsm4(bh, bAddrH + boff + kadd);
            ldsm4(bl, bAddrL + boff + kadd);
            #pragma unroll
            for (int mt = 0; mt < 2; mt++) {
                u32 ah[4], al[4];
                ldsm4(ah, aAddrH + boff + kadd + (u32)(mt*16*WPITCH));
                ldsm4(al, aAddrL + boff + kadd + (u32)(mt*16*WPITCH));
                #pragma unroll
                for (int nt = 0; nt < 2; nt++) {
                    mma_bf16(acc[mt][nt], ah, bh[2*nt], bh[2*nt+1]);
                    mma_bf16(acc[mt][nt], ah, bl[2*nt], bl[2*nt+1]);
                    mma_bf16(acc[mt][nt], al, bh[2*nt], bh[2*nt+1]);
                }
            }
        }
    }

    #pragma unroll
    for (int mt = 0; mt < 2; mt++) {
        long r0 = brow + wm*32 + mt*16 + (lane >> 2);
        long cc = wn*16 + ((lane & 3) << 1);
        #pragma unroll
        for (int nt = 0; nt < 2; nt++) {
            float2 v0 = make_float2(acc[mt][nt][0], acc[mt][nt][1]);
            float2 v1 = make_float2(acc[mt][nt][2], acc[mt][nt][3]);
            *(float2*)&C[r0 * N + cc + nt*8]     = v0;
            *(float2*)&C[(r0+8) * N + cc + nt*8] = v1;
        }
    }
}

// ---------------- fused operand prep (x convert vectorized 4-wide) ----------------
// blockIdx ranges: [0,8192) convert x (4 floats/thread); [8192,12288) W_in^T;
// [12288,14336) W_out^T; [14336,14464) W_x^T split.
__global__ void prep_fused(
    const float* __restrict__ x, __half* __restrict__ xh,
    const float* __restrict__ W_in, __half* __restrict__ winT,
    const float* __restrict__ W_out, __half* __restrict__ woutT,
    const float* __restrict__ W_x, bf16* __restrict__ wxh, bf16* __restrict__ wxl)
{
    int bi = blockIdx.x;
    const int tx = threadIdx.x, ty = threadIdx.y;
    if (bi < 8192) {
        long i = ((long)bi * 256 + ty * 32 + tx) * 4;
        float4 v = *(const float4*)(x + i);
        __half2 h0 = __floats2half2_rn(v.x, v.y);
        __half2 h1 = __floats2half2_rn(v.z, v.w);
        *(__half2*)(xh + i)     = h0;
        *(__half2*)(xh + i + 2) = h1;
        return;
    }
    bi -= 8192;
    __shared__ float t[32][33];
    if (bi < 4096) {                           // W_in [1024,4096] -> winT [4096,1024]
        const int R = 1024, Cc = 4096;
        int c0 = (bi & 127) * 32, r0 = (bi >> 7) * 32;
        #pragma unroll
        for (int i = 0; i < 32; i += 8)
            t[ty + i][tx] = W_in[(long)(r0 + ty + i) * Cc + c0 + tx];
        __syncthreads();
        #pragma unroll
        for (int i = 0; i < 32; i += 8)
            winT[(long)(c0 + ty + i) * R + r0 + tx] = __float2half_rn(t[tx][ty + i]);
        return;
    }
    bi -= 4096;
    if (bi < 2048) {                           // W_out [2048,1024] -> woutT [1024,2048]
        const int R = 2048, Cc = 1024;
        int c0 = (bi & 31) * 32, r0 = (bi >> 5) * 32;
        #pragma unroll
        for (int i = 0; i < 32; i += 8)
            t[ty + i][tx] = W_out[(long)(r0 + ty + i) * Cc + c0 + tx];
        __syncthreads();
        #pragma unroll
        for (int i = 0; i < 32; i += 8)
            woutT[(long)(c0 + ty + i) * R + r0 + tx] = __float2half_rn(t[tx][ty + i]);
        return;
    }
    bi -= 2048;
    {                                          // W_x [2048,33] -> wx[64,2048] hi/lo
        const int R = 2048, Cc = 33;
        int c0 = (bi & 1) * 32, r0 = (bi >> 1) * 32;
        #pragma unroll
        for (int i = 0; i < 32; i += 8) {
            int c = c0 + tx;
            t[ty + i][tx] = (c < Cc) ? W_x[(long)(r0 + ty + i) * Cc + c] : 0.0f;
        }
        __syncthreads();
        #pragma unroll
        for (int i = 0; i < 32; i += 8) {
            int oc = c0 + ty + i;
            float v = t[tx][ty + i];
            bf16 h = __float2bfloat16_rn(v);
            wxh[(long)oc * R + r0 + tx] = h;
            wxl[(long)oc * R + r0 + tx] = __float2bfloat16_rn(v - __bfloat162float(h));
        }
    }
}

// ---------------- tiled depthwise causal conv (K=4) + SiLU, 2-wide ----------------
#define CONV_TL 32
__global__ __launch_bounds__(256) void conv_silu_tiled(
    const __half* __restrict__ xz, const float* __restrict__ conv_w,
    const float* __restrict__ conv_b,
    bf16* __restrict__ xch, bf16* __restrict__ xcl)
{
    __shared__ __half2 sx[CONV_TL + 3][256];
    const int tid = threadIdx.x;
    const int d0 = blockIdx.x * 512 + tid * 2;
    const int l0 = blockIdx.y * CONV_TL;
    const int b  = blockIdx.z;

    #pragma unroll 5
    for (int r = 0; r < CONV_TL + 3; r++) {
        int l = l0 - 3 + r;
        sx[r][tid] = (l >= 0) ? *(const __half2*)(xz + ((long)(b * LL + l)) * (2*DINNER) + d0)
                              : __half2(__float2half(0.f), __float2half(0.f));
    }
    __syncthreads();

    const float4 w0 = *(const float4*)&conv_w[d0 * DCONV];
    const float4 w1 = *(const float4*)&conv_w[(d0+1) * DCONV];
    const float bias0 = conv_b[d0];
    const float bias1 = conv_b[d0+1];

    #pragma unroll 4
    for (int j = 0; j < CONV_TL; j++) {
        float2 t0 = __half22float2(sx[j+0][tid]);
        float2 t1 = __half22float2(sx[j+1][tid]);
        float2 t2 = __half22float2(sx[j+2][tid]);
        float2 t3 = __half22float2(sx[j+3][tid]);
        float a0 = bias0 + t0.x*w0.x + t1.x*w0.y + t2.x*w0.z + t3.x*w0.w;
        float a1 = bias1 + t0.y*w1.x + t1.y*w1.y + t2.y*w1.z + t3.y*w1.w;
        float s0 = a0 / (1.0f + __expf(-a0));
        float s1 = a1 / (1.0f + __expf(-a1));
        long idx = ((long)(b * LL + l0 + j)) * DINNER + d0;
        bf16 h0 = __float2bfloat16_rn(s0);
        bf16 h1 = __float2bfloat16_rn(s1);
        bf16 l0v = __float2bfloat16_rn(s0 - __bfloat162float(h0));
        bf16 l1v = __float2bfloat16_rn(s1 - __bfloat162float(h1));
        *(__nv_bfloat162*)(xch + idx) = __nv_bfloat162(h0, h1);
        *(__nv_bfloat162*)(xcl + idx) = __nv_bfloat162(l0v, l1v);
    }
}

// ---------------- coefficients + chunk products, fused split-K reduce ----------------
__global__ __launch_bounds__(256) void coef_ptot(
    const float* __restrict__ xdbl4, const float* __restrict__ A_log,
    float* __restrict__ coef, float* __restrict__ ptot)
{
    const size_t PSZ = (size_t)M_ROWS * 64;
    __shared__ float sa[CHL][16];
    const int c = blockIdx.x, b = blockIdx.y, tid = threadIdx.x;
    const int n = tid & 15;
    const long lbase = (long)b * LL + c * CHL;
    const float Aneg = -expf(A_log[n]);

    for (int r0 = 0; r0 < CHL; r0 += 16) {
        int rloc = r0 + (tid >> 4);
        long r = lbase + rloc;
        const float* xr = xdbl4 + r * 64;
        float v  = ((xr[0]    + xr[PSZ])      + (xr[2*PSZ]      + xr[3*PSZ]));
        float bb = ((xr[1+n]  + xr[PSZ+1+n])  + (xr[2*PSZ+1+n]  + xr[3*PSZ+1+n]));
        float cc = ((xr[17+n] + xr[PSZ+17+n]) + (xr[2*PSZ+17+n] + xr[3*PSZ+17+n]));
        float delta = (v > 20.0f) ? v : log1pf(expf(v));
        float abar = expf(delta * Aneg);
        float* o = coef + r * 48;
        o[n]      = abar;
        o[16 + n] = delta * bb;
        o[32 + n] = cc;
        sa[rloc][n] = abar;
    }
    __syncthreads();
    if (tid < 16) {
        float p = 1.0f;
        #pragma unroll 8
        for (int l = 0; l < CHL; l++) p *= sa[l][tid];
        ptot[(b*NCH + c)*16 + tid] = p;
    }
}

// ---------------- scan pass 1: 2-wide ----------------
__global__ __launch_bounds__(256) void scan_pass1(
    const float* __restrict__ coef, const bf16* __restrict__ xch,
    const bf16* __restrict__ xcl, float* __restrict__ hend)
{
    __shared__ float sca[CHL*32];
    int b = blockIdx.z, c = blockIdx.y, tid = threadIdx.x;
    int d0 = blockIdx.x * 512 + tid * 2;
    long lbase = (long)b * LL + c * CHL;
    for (int i = tid; i < CHL*32; i += 256) {
        int row = i >> 5, j = i & 31;
        sca[i] = coef[(lbase + row)*48 + j];
    }
    __syncthreads();
    u64 ha[8], hb[8];
    #pragma unroll
    for (int j = 0; j < 8; j++) { ha[j] = 0ull; hb[j] = 0ull; }
    for (int l = 0; l < CHL; l++) {
        long ix = (lbase + l)*DINNER + d0;
        float2 fh = __bfloat1622float2(*(const __nv_bfloat162*)(xch + ix));
        float2 fl = __bfloat1622float2(*(const __nv_bfloat162*)(xcl + ix));
        float xa = fh.x + fl.x, xb = fh.y + fl.y;
        u64 xxa = pk2(xa, xa), xxb = pk2(xb, xb);
        const u64* ap = (const u64*)&sca[l*32];
        #pragma unroll
        for (int j = 0; j < 8; j++) {
            ha[j] = fma2(ap[j], ha[j], mul2(ap[8+j], xxa));
            hb[j] = fma2(ap[j], hb[j], mul2(ap[8+j], xxb));
        }
    }
    float* o = hend + (((long)(b*NCH + c) * DINNER) + d0) * 16;
    #pragma unroll
    for (int j = 0; j < 8; j++) {
        float x0, x1; up2(x0, x1, ha[j]);
        o[2*j] = x0; o[2*j+1] = x1;
    }
    #pragma unroll
    for (int j = 0; j < 8; j++) {
        float x0, x1; up2(x0, x1, hb[j]);
        o[16 + 2*j] = x0; o[16 + 2*j+1] = x1;
    }
}

// ---------------- scan pass 2 ----------------
__global__ __launch_bounds__(256) void scan_pass2(
    const float* __restrict__ hend, const float* __restrict__ ptot,
    float* __restrict__ hstart)
{
    long idx = (long)blockIdx.x * 256 + threadIdx.x;
    int n = (int)(idx & 15);
    int d = (int)((idx >> 4) & (DINNER-1));
    int b = (int)(idx >> 15);
    float hs = 0.0f;
    for (int c = 0; c < NCH; c++) {
        long o = (((long)(b*NCH + c) * DINNER) + d) * 16 + n;
        hstart[o] = hs;
        hs = ptot[(b*NCH + c)*16 + n] * hs + hend[o];
    }
}

// ---------------- scan pass 3: 2-wide ----------------
__global__ __launch_bounds__(256) void scan_pass3(
    const float* __restrict__ coef, const float* __restrict__ hstart,
    const bf16* __restrict__ xch, const bf16* __restrict__ xcl,
    const __half* __restrict__ xz, const float* __restrict__ Dp,
    __half* __restrict__ yh)
{
    __shared__ float sc[CHL*48];
    int b = blockIdx.z, c = blockIdx.y, tid = threadIdx.x;
    int d0 = blockIdx.x * 512 + tid * 2;
    long lbase = (long)b * LL + c * CHL;
    for (int i = tid; i < CHL*48; i += 256)
        sc[i] = coef[lbase*48 + i];
    __syncthreads();

    u64 ha[8], hb[8];
    const u64* hsp = (const u64*)(hstart + (((long)(b*NCH + c) * DINNER) + d0) * 16);
    #pragma unroll
    for (int j = 0; j < 8; j++) { ha[j] = hsp[j]; hb[j] = hsp[8 + j]; }
    float Da = Dp[d0], Db = Dp[d0+1];

    for (int l = 0; l < CHL; l++) {
        long row = lbase + l;
        long ix = row*DINNER + d0;
        float2 fh = __bfloat1622float2(*(const __nv_bfloat162*)(xch + ix));
        float2 fl = __bfloat1622float2(*(const __nv_bfloat162*)(xcl + ix));
        float xa = fh.x + fl.x, xb = fh.y + fl.y;
        float2 zf = __half22float2(*(const __half2*)(xz + row*(2*DINNER) + DINNER + d0));
        u64 xxa = pk2(xa, xa), xxb = pk2(xb, xb);
        const u64* ap = (const u64*)&sc[l*48];
        u64 ya = 0ull, yb = 0ull;
        #pragma unroll
        for (int j = 0; j < 8; j++) {
            ha[j] = fma2(ap[j], ha[j], mul2(ap[8+j], xxa));
            hb[j] = fma2(ap[j], hb[j], mul2(ap[8+j], xxb));
            ya = fma2(ha[j], ap[16+j], ya);
            yb = fma2(hb[j], ap[16+j], yb);
        }
        float a0, a1, b0, b1;
        up2(a0, a1, ya); up2(b0, b1, yb);
        float vy0 = a0 + a1 + xa * Da;
        float vy1 = b0 + b1 + xb * Db;
        float sg0 = zf.x / (1.0f + __expf(-zf.x));
        float sg1 = zf.y / (1.0f + __expf(-zf.y));
        *(__half2*)(yh + ix) = __floats2half2_rn(vy0 * sg0, vy1 * sg1);
    }
}

// ---------------- launch ----------------
extern "C" void kernel_launch(void* const* d_in, const int* in_sizes, int n_in,
                              void* d_out, int out_size)
{
    const float* x       = (const float*)d_in[0];
    const float* W_in    = (const float*)d_in[1];
    const float* conv_w  = (const float*)d_in[2];
    const float* conv_b  = (const float*)d_in[3];
    const float* W_x     = (const float*)d_in[4];
    const float* A_log   = (const float*)d_in[5];
    const float* D_param = (const float*)d_in[6];
    const float* W_out   = (const float*)d_in[7];
    float* out = (float*)d_out;

    float *coefp, *xdbl4, *ptot, *hend, *hstart;
    __half *xzh, *xh, *winT, *woutT, *yh;
    bf16 *xch, *xcl, *wxh, *wxl;
    cudaGetSymbolAddress((void**)&xzh,   g_xzh);
    cudaGetSymbolAddress((void**)&coefp, g_coef);
    cudaGetSymbolAddress((void**)&xdbl4, g_xdbl4);
    cudaGetSymbolAddress((void**)&ptot,  g_ptot);
    cudaGetSymbolAddress((void**)&hend,  g_hend);
    cudaGetSymbolAddress((void**)&hstart,g_hstart);
    cudaGetSymbolAddress((void**)&xh,    g_xh);
    cudaGetSymbolAddress((void**)&winT,  g_winT);
    cudaGetSymbolAddress((void**)&woutT, g_woutT);
    cudaGetSymbolAddress((void**)&xch,   g_xch);
    cudaGetSymbolAddress((void**)&xcl,   g_xcl);
    cudaGetSymbolAddress((void**)&wxh,   g_wxT_h);
    cudaGetSymbolAddress((void**)&wxl,   g_wxT_l);
    cudaGetSymbolAddress((void**)&yh,    g_yh);

    const int SMEM1 = 3 * (2*128*PITCH);         // 110592
    const int SMEMW = 3 * (4*64*WPITCH);         // 61440
    cudaFuncSetAttribute((const void*)gemm_f16<__half>, cudaFuncAttributeMaxDynamicSharedMemorySize, SMEM1);
    cudaFuncSetAttribute((const void*)gemm_f16<float>,  cudaFuncAttributeMaxDynamicSharedMemorySize, SMEM1);
    cudaFuncSetAttribute((const void*)gemm_wx64,        cudaFuncAttributeMaxDynamicSharedMemorySize, SMEMW);

    // 1) fused operand prep (vectorized convert + transposes + wx split)
    prep_fused<<<8192 + 4096 + 2048 + 128, dim3(32,8)>>>(
        x, xh, W_in, winT, W_out, woutT, W_x, wxh, wxl);
    // 2) GEMM1: xz(fp16) = x @ W_in
    gemm_f16<__half><<<dim3(4096/128, 8192/128), 256, SMEM1>>>(
        (const u16*)xh, (const u16*)winT, xzh, 4096, 1024);
    // 3) conv + silu (2-wide)
    conv_silu_tiled<<<dim3(DINNER/512, LL/CONV_TL, BB), 256>>>(
        xzh, conv_w, conv_b, xch, xcl);
    // 4) x_dbl partials = xc @ W_x  (split-K x4)
    gemm_wx64<<<dim3(KSPLIT, 8192/64), 256, SMEMW>>>(
        (const u16*)xch, (const u16*)xcl, (const u16*)wxh, (const u16*)wxl, xdbl4, 64, 2048);
    // 5) coefficients + chunk products (fused split-K reduce)
    coef_ptot<<<dim3(NCH, BB), 256>>>(xdbl4, A_log, coefp, ptot);
    // 6-8) chunked parallel scan
    scan_pass1<<<dim3(DINNER/512, NCH, BB), 256>>>(coefp, xch, xcl, hend);
    scan_pass2<<<(BB*DINNER*DSTATE)/256, 256>>>(hend, ptot, hstart);
    scan_pass3<<<dim3(DINNER/512, NCH, BB), 256>>>(coefp, hstart, xch, xcl, xzh, D_param, yh);
    // 9) out = y @ W_out
    gemm_f16<float><<<dim3(1024/128, 8192/128), 256, SMEM1>>>(
        (const u16*)yh, (const u16*)woutT, out, 1024, 2048);
}

// round 16
// speedup vs baseline: 1.1350x; 1.0176x over previous
#include <cuda_runtime.h>
#include <cuda_bf16.h>
#include <cuda_fp16.h>
#include <math.h>
#include <stdint.h>

#define BB 4
#define LL 2048
#define DMODEL 1024
#define DSTATE 16
#define DCONV 4
#define DINNER 2048
#define M_ROWS (BB*LL)            // 8192
#define NCH 16
#define CHL 128
#define KSPLIT 4

typedef unsigned int u32;
typedef unsigned long long u64;
typedef __nv_bfloat16 bf16;
typedef uint16_t u16;

// ---------------- scratch (device globals) ----------------
__device__ __align__(16) __half g_xzh[(size_t)M_ROWS * (2*DINNER)];
__device__ __align__(16) __half g_xh[(size_t)M_ROWS * DMODEL];
__device__ __align__(16) __half g_winT[(size_t)(2*DINNER) * DMODEL];
__device__ __align__(16) bf16  g_xch[(size_t)M_ROWS * DINNER];
__device__ __align__(16) bf16  g_xcl[(size_t)M_ROWS * DINNER];
__device__ __align__(16) bf16  g_wxT_h[64 * DINNER];
__device__ __align__(16) bf16  g_wxT_l[64 * DINNER];
__device__ __align__(16) float g_xdbl4[(size_t)KSPLIT * M_ROWS * 64];
__device__ __align__(16) float g_coef[(size_t)M_ROWS * 48];
__device__ __align__(16) float g_ptot[BB * NCH * DSTATE];
__device__ __align__(16) float g_hend[(size_t)BB * NCH * DINNER * DSTATE];
__device__ __align__(16) float g_hstart[(size_t)BB * NCH * DINNER * DSTATE];
__device__ __align__(16) __half g_yh[(size_t)M_ROWS * DINNER];
__device__ __align__(16) __half g_woutT[(size_t)DMODEL * DINNER];

// ---------------- PTX helpers (BASE PTX ONLY) ----------------
__device__ __forceinline__ u32 smem_u32(const void* p) {
    u32 a; asm("{ .reg .u64 t; cvta.to.shared.u64 t, %1; cvt.u32.u64 %0, t; }" : "=r"(a) : "l"(p));
    return a;
}
__device__ __forceinline__ void cp16(u32 dst, const void* src) {
    asm volatile("cp.async.cg.shared.global [%0], [%1], 16;" :: "r"(dst), "l"(src));
}
__device__ __forceinline__ void cp_commit() {
    asm volatile("cp.async.commit_group;" ::: "memory");
}
__device__ __forceinline__ void ldsm4(u32* r, u32 addr) {
    asm volatile("ldmatrix.sync.aligned.m8n8.x4.shared.b16 {%0,%1,%2,%3}, [%4];"
                 : "=r"(r[0]), "=r"(r[1]), "=r"(r[2]), "=r"(r[3]) : "r"(addr));
}
__device__ __forceinline__ void mma_bf16(float* d, const u32* a, const u32 b0, const u32 b1) {
    asm volatile(
        "mma.sync.aligned.m16n8k16.row.col.f32.bf16.bf16.f32 "
        "{%0,%1,%2,%3}, {%4,%5,%6,%7}, {%8,%9}, {%0,%1,%2,%3};"
        : "+f"(d[0]), "+f"(d[1]), "+f"(d[2]), "+f"(d[3])
        : "r"(a[0]), "r"(a[1]), "r"(a[2]), "r"(a[3]), "r"(b0), "r"(b1));
}
__device__ __forceinline__ void mma_f16(float* d, const u32* a, const u32 b0, const u32 b1) {
    asm volatile(
        "mma.sync.aligned.m16n8k16.row.col.f32.f16.f16.f32 "
        "{%0,%1,%2,%3}, {%4,%5,%6,%7}, {%8,%9}, {%0,%1,%2,%3};"
        : "+f"(d[0]), "+f"(d[1]), "+f"(d[2]), "+f"(d[3])
        : "r"(a[0]), "r"(a[1]), "r"(a[2]), "r"(a[3]), "r"(b0), "r"(b1));
}
__device__ __forceinline__ u64 pk2(float a, float b) {
    u64 r; asm("mov.b64 %0, {%1, %2};" : "=l"(r) : "f"(a), "f"(b)); return r;
}
__device__ __forceinline__ void up2(float& a, float& b, u64 v) {
    asm("mov.b64 {%0, %1}, %2;" : "=f"(a), "=f"(b) : "l"(v));
}
__device__ __forceinline__ u64 mul2(u64 a, u64 b) {
    u64 d; asm("mul.rn.f32x2 %0, %1, %2;" : "=l"(d) : "l"(a), "l"(b)); return d;
}
__device__ __forceinline__ u64 fma2(u64 a, u64 b, u64 c) {
    u64 d; asm("fma.rn.f32x2 %0, %1, %2, %3;" : "=l"(d) : "l"(a), "l"(b), "l"(c)); return d;
}

// ---------------- fp16 1-product HMMA GEMM, cp.async spread across kk ----------------
#define PITCH 144

template<typename OutT>
__global__ __launch_bounds__(256, 2) void gemm_f16(
    const u16* __restrict__ Ah, const u16* __restrict__ Bh,
    OutT* __restrict__ C, int N, int K)
{
    constexpr int ABYT = 128 * PITCH;
    constexpr int STAGE = 2 * ABYT;

    extern __shared__ __align__(16) char smem[];
    const u32 sb = smem_u32(smem);

    const int tid = threadIdx.x;
    const long brow = (long)blockIdx.y * 128;
    const long bcol = (long)blockIdx.x * 128;

    const int wid  = tid >> 5;
    const int lane = tid & 31;
    const int wm = wid & 1;
    const int wn = wid >> 1;

    const int a_row  = lane & 15;
    const int a_colb = (lane >> 4) * 16;
    const int q = lane >> 3;
    const int b_n  = (lane & 7) + ((q >> 1) << 3);
    const int b_kb = (q & 1) * 16;

    const u32 aAddr = sb + (u32)((wm*64 + a_row) * PITCH + a_colb);
    const u32 bAddr = sb + ABYT + (u32)((wn*32 + b_n) * PITCH + b_kb);

    float acc[4][4][4];
    #pragma unroll
    for (int i = 0; i < 4; i++)
        #pragma unroll
        for (int j = 0; j < 4; j++)
            #pragma unroll
            for (int v = 0; v < 4; v++) acc[i][j][v] = 0.0f;

    const int nst = K >> 6;

    auto load_quarter = [&](int s, int qtr) {
        const u32 base = sb + (u32)((s % 3) * STAGE);
        const int kt = s << 6;
        int i = tid + qtr * 256;
        int r = i >> 3, ch = i & 7;
        u32 d = base + (u32)(r * PITCH + ch * 16);
        cp16(d, Ah + (brow + r) * (long)K + kt + ch * 8);
        cp16(d + ABYT, Bh + (bcol + r) * (long)K + kt + ch * 8);
    };
    auto load_stage = [&](int s) {
        #pragma unroll
        for (int qtr = 0; qtr < 4; qtr++) load_quarter(s, qtr);
        cp_commit();
    };

    load_stage(0);
    load_stage(1);

    u32 afr[2][4];
    u32 bfr[2][2][4];

    for (int s = 0; s < nst; s++) {
        if (s + 1 < nst) asm volatile("cp.async.wait_group 1;" ::: "memory");
        else             asm volatile("cp.async.wait_group 0;" ::: "memory");
        __syncthreads();

        const u32 boff = (u32)((s % 3) * STAGE);
        const bool more = (s + 2 < nst);

        ldsm4(bfr[0][0], bAddr + boff);
        ldsm4(bfr[0][1], bAddr + boff + 16*PITCH);
        ldsm4(afr[0],    aAddr + boff);

        #pragma unroll
        for (int kk = 0; kk < 4; kk++) {
            const int cb = kk & 1;
            const u32 kadd0 = kk * 32;
            if (more) load_quarter(s + 2, kk);
            if (kk == 3 && more) cp_commit();
            if (kk < 3) {
                const u32 kadd = (kk + 1) * 32;
                ldsm4(bfr[cb^1][0], bAddr + boff + kadd);
                ldsm4(bfr[cb^1][1], bAddr + boff + kadd + 16*PITCH);
            }
            #pragma unroll
            for (int mt = 0; mt < 4; mt++) {
                const int ca = (kk * 4 + mt) & 1;
                if (mt < 3)
                    ldsm4(afr[ca^1], aAddr + boff + kadd0 + (u32)((mt+1)*16*PITCH));
                else if (kk < 3)
                    ldsm4(afr[ca^1], aAddr + boff + (u32)((kk+1)*32));
                #pragma unroll
                for (int nt = 0; nt < 4; nt++) {
                    const int p = nt >> 1, h = nt & 1;
                    mma_f16(acc[mt][nt], afr[ca], bfr[cb][p][2*h], bfr[cb][p][2*h+1]);
                }
            }
        }
        if (!more) { if (s + 2 == nst) cp_commit(); }
    }

    #pragma unroll
    for (int mt = 0; mt < 4; mt++) {
        long r0 = brow + wm*64 + mt*16 + (lane >> 2);
        long cc = bcol + wn*32 + ((lane & 3) << 1);
        #pragma unroll
        for (int nt = 0; nt < 4; nt++) {
            if (sizeof(OutT) == 2) {
                __half2* p0 = (__half2*)((__half*)C + r0 * N + cc + nt*8);
                __half2* p1 = (__half2*)((__half*)C + (r0+8) * N + cc + nt*8);
                *p0 = __floats2half2_rn(acc[mt][nt][0], acc[mt][nt][1]);
                *p1 = __floats2half2_rn(acc[mt][nt][2], acc[mt][nt][3]);
            } else {
                float2 v0 = make_float2(acc[mt][nt][0], acc[mt][nt][1]);
                float2 v1 = make_float2(acc[mt][nt][2], acc[mt][nt][3]);
                *(float2*)((float*)C + r0 * N + cc + nt*8)     = v0;
                *(float2*)((float*)C + (r0+8) * N + cc + nt*8) = v1;
            }
        }
    }
}

// ---------------- wx GEMM: 64x64 tile, bf16 3-product, SPLIT-K x4 ----------------
#define WPITCH 80

__global__ __launch_bounds__(256, 3) void gemm_wx64(
    const u16* __restrict__ Ah, const u16* __restrict__ Al,
    const u16* __restrict__ Bh, const u16* __restrict__ Bl,
    float* __restrict__ Cpart, int N, int K)
{
    constexpr int ABYT = 64 * WPITCH;
    constexpr int OFF_AL = ABYT;
    constexpr int OFF_BH = 2 * ABYT;
    constexpr int OFF_BL = 3 * ABYT;
    constexpr int STAGE = 4 * ABYT;

    extern __shared__ __align__(16) char smem[];
    const u32 sb = smem_u32(smem);

    const int tid = threadIdx.x;
    const int kp  = blockIdx.x;
    const long brow = (long)blockIdx.y * 64;
    const int kbase = kp * (K / KSPLIT);
    float* C = Cpart + (size_t)kp * M_ROWS * 64;

    const int wid  = tid >> 5;
    const int lane = tid & 31;
    const int wm = wid & 1;
    const int wn = wid >> 1;

    const int a_row  = lane & 15;
    const int a_colb = (lane >> 4) * 16;
    const int q = lane >> 3;
    const int b_n  = (lane & 7) + ((q >> 1) << 3);
    const int b_kb = (q & 1) * 16;

    const u32 aAddrH = sb + (u32)((wm*32 + a_row) * WPITCH + a_colb);
    const u32 aAddrL = aAddrH + OFF_AL;
    const u32 bAddrH = sb + OFF_BH + (u32)((wn*16 + b_n) * WPITCH + b_kb);
    const u32 bAddrL = bAddrH + ABYT;

    float acc[2][2][4];
    #pragma unroll
    for (int i = 0; i < 2; i++)
        #pragma unroll
        for (int j = 0; j < 2; j++)
            #pragma unroll
            for (int v = 0; v < 4; v++) acc[i][j][v] = 0.0f;

    const int nst = (K / KSPLIT) >> 5;

    auto load_stage = [&](int s) {
        const u32 base = sb + (u32)((s % 3) * STAGE);
        const int kt = kbase + (s << 5);
        {
            int i = tid;
            int r = i >> 2, ch = i & 3;
            u32 d = base + (u32)(r * WPITCH + ch * 16);
            long g = (brow + r) * (long)K + kt + ch * 8;
            cp16(d, Ah + g);
            cp16(d + OFF_AL, Al + g);
            long gb = (long)r * K + kt + ch * 8;
            cp16(d + OFF_BH, Bh + gb);
            cp16(d + OFF_BL, Bl + gb);
        }
        cp_commit();
    };

    load_stage(0);
    load_stage(1);

    for (int s = 0; s < nst; s++) {
        if (s + 1 < nst) asm volatile("cp.async.wait_group 1;" ::: "memory");
        else             asm volatile("cp.async.wait_group 0;" ::: "memory");
        __syncthreads();
        if (s + 2 < nst) load_stage(s + 2);

        const u32 boff = (u32)((s % 3) * STAGE);
        #pragma unroll
        for (int kk = 0; kk < 2; kk++) {
            const u32 kadd = kk * 32;
            u32 bh[4], bl[4];
            ldsm4(bh, bAddrH + boff + kadd);
            ldsm4(bl, bAddrL + boff + kadd);
            #pragma unroll
            for (int mt = 0; mt < 2; mt++) {
                u32 ah[4], al[4];
                ldsm4(ah, aAddrH + boff + kadd + (u32)(mt*16*WPITCH));
                ldsm4(al, aAddrL + boff + kadd + (u32)(mt*16*WPITCH));
                #pragma unroll
                for (int nt = 0; nt < 2; nt++) {
                    mma_bf16(acc[mt][nt], ah, bh[2*nt], bh[2*nt+1]);
                    mma_bf16(acc[mt][nt], ah, bl[2*nt], bl[2*nt+1]);
                    mma_bf16(acc[mt][nt], al, bh[2*nt], bh[2*nt+1]);
                }
            }
        }
    }

    #pragma unroll
    for (int mt = 0; mt < 2; mt++) {
        long r0 = brow + wm*32 + mt*16 + (lane >> 2);
        long cc = wn*16 + ((lane & 3) << 1);
        #pragma unroll
        for (int nt = 0; nt < 2; nt++) {
            float2 v0 = make_float2(acc[mt][nt][0], acc[mt][nt][1]);
            float2 v1 = make_float2(acc[mt][nt][2], acc[mt][nt][3]);
            *(float2*)&C[r0 * N + cc + nt*8]     = v0;
            *(float2*)&C[(r0+8) * N + cc + nt*8] = v1;
        }
    }
}

// ---------------- fused operand prep (x convert vectorized 4-wide) ----------------
__global__ void prep_fused(
    const float* __restrict__ x, __half* __restrict__ xh,
    const float* __restrict__ W_in, __half* __restrict__ winT,
    const float* __restrict__ W_out, __half* __restrict__ woutT,
    const float* __restrict__ W_x, bf16* __restrict__ wxh, bf16* __restrict__ wxl)
{
    int bi = blockIdx.x;
    const int tx = threadIdx.x, ty = threadIdx.y;
    if (bi < 8192) {
        long i = ((long)bi * 256 + ty * 32 + tx) * 4;
        float4 v = *(const float4*)(x + i);
        __half2 h0 = __floats2half2_rn(v.x, v.y);
        __half2 h1 = __floats2half2_rn(v.z, v.w);
        *(__half2*)(xh + i)     = h0;
        *(__half2*)(xh + i + 2) = h1;
        return;
    }
    bi -= 8192;
    __shared__ float t[32][33];
    if (bi < 4096) {
        const int R = 1024, Cc = 4096;
        int c0 = (bi & 127) * 32, r0 = (bi >> 7) * 32;
        #pragma unroll
        for (int i = 0; i < 32; i += 8)
            t[ty + i][tx] = W_in[(long)(r0 + ty + i) * Cc + c0 + tx];
        __syncthreads();
        #pragma unroll
        for (int i = 0; i < 32; i += 8)
            winT[(long)(c0 + ty + i) * R + r0 + tx] = __float2half_rn(t[tx][ty + i]);
        return;
    }
    bi -= 4096;
    if (bi < 2048) {
        const int R = 2048, Cc = 1024;
        int c0 = (bi & 31) * 32, r0 = (bi >> 5) * 32;
        #pragma unroll
        for (int i = 0; i < 32; i += 8)
            t[ty + i][tx] = W_out[(long)(r0 + ty + i) * Cc + c0 + tx];
        __syncthreads();
        #pragma unroll
        for (int i = 0; i < 32; i += 8)
            woutT[(long)(c0 + ty + i) * R + r0 + tx] = __float2half_rn(t[tx][ty + i]);
        return;
    }
    bi -= 2048;
    {
        const int R = 2048, Cc = 33;
        int c0 = (bi & 1) * 32, r0 = (bi >> 1) * 32;
        #pragma unroll
        for (int i = 0; i < 32; i += 8) {
            int c = c0 + tx;
            t[ty + i][tx] = (c < Cc) ? W_x[(long)(r0 + ty + i) * Cc + c] : 0.0f;
        }
        __syncthreads();
        #pragma unroll
        for (int i = 0; i < 32; i += 8) {
            int oc = c0 + ty + i;
            float v = t[tx][ty + i];
            bf16 h = __float2bfloat16_rn(v);
            wxh[(long)oc * R + r0 + tx] = h;
            wxl[(long)oc * R + r0 + tx] = __float2bfloat16_rn(v - __bfloat162float(h));
        }
    }
}

// ---------------- tiled depthwise causal conv (K=4) + SiLU, 2-wide ----------------
#define CONV_TL 32
__global__ __launch_bounds__(256) void conv_silu_tiled(
    const __half* __restrict__ xz, const float* __restrict__ conv_w,
    const float* __restrict__ conv_b,
    bf16* __restrict__ xch, bf16* __restrict__ xcl)
{
    __shared__ __half2 sx[CONV_TL + 3][256];
    const int tid = threadIdx.x;
    const int d0 = blockIdx.x * 512 + tid * 2;
    const int l0 = blockIdx.y * CONV_TL;
    const int b  = blockIdx.z;

    #pragma unroll 5
    for (int r = 0; r < CONV_TL + 3; r++) {
        int l = l0 - 3 + r;
        sx[r][tid] = (l >= 0) ? *(const __half2*)(xz + ((long)(b * LL + l)) * (2*DINNER) + d0)
                              : __half2(__float2half(0.f), __float2half(0.f));
    }
    __syncthreads();

    const float4 w0 = *(const float4*)&conv_w[d0 * DCONV];
    const float4 w1 = *(const float4*)&conv_w[(d0+1) * DCONV];
    const float bias0 = conv_b[d0];
    const float bias1 = conv_b[d0+1];

    #pragma unroll 4
    for (int j = 0; j < CONV_TL; j++) {
        float2 t0 = __half22float2(sx[j+0][tid]);
        float2 t1 = __half22float2(sx[j+1][tid]);
        float2 t2 = __half22float2(sx[j+2][tid]);
        float2 t3 = __half22float2(sx[j+3][tid]);
        float a0 = bias0 + t0.x*w0.x + t1.x*w0.y + t2.x*w0.z + t3.x*w0.w;
        float a1 = bias1 + t0.y*w1.x + t1.y*w1.y + t2.y*w1.z + t3.y*w1.w;
        float s0 = a0 / (1.0f + __expf(-a0));
        float s1 = a1 / (1.0f + __expf(-a1));
        long idx = ((long)(b * LL + l0 + j)) * DINNER + d0;
        bf16 h0 = __float2bfloat16_rn(s0);
        bf16 h1 = __float2bfloat16_rn(s1);
        bf16 l0v = __float2bfloat16_rn(s0 - __bfloat162float(h0));
        bf16 l1v = __float2bfloat16_rn(s1 - __bfloat162float(h1));
        *(__nv_bfloat162*)(xch + idx) = __nv_bfloat162(h0, h1);
        *(__nv_bfloat162*)(xcl + idx) = __nv_bfloat162(l0v, l1v);
    }
}

// ---------------- MERGED: coefficients (+coef/ptot store) + scan pass 1 ----------------
// grid (DINNER/512, NCH, BB). Every CTA recomputes its chunk's (a, bb) from the
// split-K partials into smem; d-block 0 additionally writes coef rows (for p3)
// and ptot (for p2). Arithmetic identical to the old coef_ptot + scan_pass1.
__global__ __launch_bounds__(256) void scan_pass1_coef(
    const float* __restrict__ xdbl4, const float* __restrict__ A_log,
    float* __restrict__ coef, float* __restrict__ ptot,
    const bf16* __restrict__ xch, const bf16* __restrict__ xcl,
    float* __restrict__ hend)
{
    const size_t PSZ = (size_t)M_ROWS * 64;
    __shared__ float sca[CHL*32];      // per row: a[16], bb[16]
    const int dblk = blockIdx.x, c = blockIdx.y, b = blockIdx.z;
    const int tid = threadIdx.x;
    const int n = tid & 15;
    const long lbase = (long)b * LL + c * CHL;
    const float Aneg = -expf(A_log[n]);

    for (int r0 = 0; r0 < CHL; r0 += 16) {
        int rloc = r0 + (tid >> 4);
        long r = lbase + rloc;
        const float* xr = xdbl4 + r * 64;
        float v  = ((xr[0]    + xr[PSZ])      + (xr[2*PSZ]      + xr[3*PSZ]));
        float bb = ((xr[1+n]  + xr[PSZ+1+n])  + (xr[2*PSZ+1+n]  + xr[3*PSZ+1+n]));
        float delta = (v > 20.0f) ? v : log1pf(expf(v));
        float abar = expf(delta * Aneg);
        float bbar = delta * bb;
        sca[rloc*32 + n]      = abar;
        sca[rloc*32 + 16 + n] = bbar;
        if (dblk == 0) {
            float cc = ((xr[17+n] + xr[PSZ+17+n]) + (xr[2*PSZ+17+n] + xr[3*PSZ+17+n]));
            float* o = coef + r * 48;
            o[n]      = abar;
            o[16 + n] = bbar;
            o[32 + n] = cc;
        }
    }
    __syncthreads();
    if (dblk == 0 && tid < 16) {
        float p = 1.0f;
        #pragma unroll 8
        for (int l = 0; l < CHL; l++) p *= sca[l*32 + tid];
        ptot[(b*NCH + c)*16 + tid] = p;
    }

    // local chunk scan from h=0 (2-wide over d)
    int d0 = dblk * 512 + tid * 2;
    u64 ha[8], hb[8];
    #pragma unroll
    for (int j = 0; j < 8; j++) { ha[j] = 0ull; hb[j] = 0ull; }
    for (int l = 0; l < CHL; l++) {
        long ix = (lbase + l)*DINNER + d0;
        float2 fh = __bfloat1622float2(*(const __nv_bfloat162*)(xch + ix));
        float2 fl = __bfloat1622float2(*(const __nv_bfloat162*)(xcl + ix));
        float xa = fh.x + fl.x, xb = fh.y + fl.y;
        u64 xxa = pk2(xa, xa), xxb = pk2(xb, xb);
        const u64* ap = (const u64*)&sca[l*32];
        #pragma unroll
        for (int j = 0; j < 8; j++) {
            ha[j] = fma2(ap[j], ha[j], mul2(ap[8+j], xxa));
            hb[j] = fma2(ap[j], hb[j], mul2(ap[8+j], xxb));
        }
    }
    float* o = hend + (((long)(b*NCH + c) * DINNER) + d0) * 16;
    #pragma unroll
    for (int j = 0; j < 8; j++) {
        float x0, x1; up2(x0, x1, ha[j]);
        o[2*j] = x0; o[2*j+1] = x1;
    }
    #pragma unroll
    for (int j = 0; j < 8; j++) {
        float x0, x1; up2(x0, x1, hb[j]);
        o[16 + 2*j] = x0; o[16 + 2*j+1] = x1;
    }
}

// ---------------- scan pass 2 ----------------
__global__ __launch_bounds__(256) void scan_pass2(
    const float* __restrict__ hend, const float* __restrict__ ptot,
    float* __restrict__ hstart)
{
    long idx = (long)blockIdx.x * 256 + threadIdx.x;
    int n = (int)(idx & 15);
    int d = (int)((idx >> 4) & (DINNER-1));
    int b = (int)(idx >> 15);
    float hs = 0.0f;
    for (int c = 0; c < NCH; c++) {
        long o = (((long)(b*NCH + c) * DINNER) + d) * 16 + n;
        hstart[o] = hs;
        hs = ptot[(b*NCH + c)*16 + n] * hs + hend[o];
    }
}

// ---------------- scan pass 3: 2-wide ----------------
__global__ __launch_bounds__(256) void scan_pass3(
    const float* __restrict__ coef, const float* __restrict__ hstart,
    const bf16* __restrict__ xch, const bf16* __restrict__ xcl,
    const __half* __restrict__ xz, const float* __restrict__ Dp,
    __half* __restrict__ yh)
{
    __shared__ float sc[CHL*48];
    int b = blockIdx.z, c = blockIdx.y, tid = threadIdx.x;
    int d0 = blockIdx.x * 512 + tid * 2;
    long lbase = (long)b * LL + c * CHL;
    for (int i = tid; i < CHL*48; i += 256)
        sc[i] = coef[lbase*48 + i];
    __syncthreads();

    u64 ha[8], hb[8];
    const u64* hsp = (const u64*)(hstart + (((long)(b*NCH + c) * DINNER) + d0) * 16);
    #pragma unroll
    for (int j = 0; j < 8; j++) { ha[j] = hsp[j]; hb[j] = hsp[8 + j]; }
    float Da = Dp[d0], Db = Dp[d0+1];

    for (int l = 0; l < CHL; l++) {
        long row = lbase + l;
        long ix = row*DINNER + d0;
        float2 fh = __bfloat1622float2(*(const __nv_bfloat162*)(xch + ix));
        float2 fl = __bfloat1622float2(*(const __nv_bfloat162*)(xcl + ix));
        float xa = fh.x + fl.x, xb = fh.y + fl.y;
        float2 zf = __half22float2(*(const __half2*)(xz + row*(2*DINNER) + DINNER + d0));
        u64 xxa = pk2(xa, xa), xxb = pk2(xb, xb);
        const u64* ap = (const u64*)&sc[l*48];
        u64 ya = 0ull, yb = 0ull;
        #pragma unroll
        for (int j = 0; j < 8; j++) {
            ha[j] = fma2(ap[j], ha[j], mul2(ap[8+j], xxa));
            hb[j] = fma2(ap[j], hb[j], mul2(ap[8+j], xxb));
            ya = fma2(ha[j], ap[16+j], ya);
            yb = fma2(hb[j], ap[16+j], yb);
        }
        float a0, a1, b0, b1;
        up2(a0, a1, ya); up2(b0, b1, yb);
        float vy0 = a0 + a1 + xa * Da;
        float vy1 = b0 + b1 + xb * Db;
        float sg0 = zf.x / (1.0f + __expf(-zf.x));
        float sg1 = zf.y / (1.0f + __expf(-zf.y));
        *(__half2*)(yh + ix) = __floats2half2_rn(vy0 * sg0, vy1 * sg1);
    }
}

// ---------------- launch ----------------
extern "C" void kernel_launch(void* const* d_in, const int* in_sizes, int n_in,
                              void* d_out, int out_size)
{
    const float* x       = (const float*)d_in[0];
    const float* W_in    = (const float*)d_in[1];
    const float* conv_w  = (const float*)d_in[2];
    const float* conv_b  = (const float*)d_in[3];
    const float* W_x     = (const float*)d_in[4];
    const float* A_log   = (const float*)d_in[5];
    const float* D_param = (const float*)d_in[6];
    const float* W_out   = (const float*)d_in[7];
    float* out = (float*)d_out;

    float *coefp, *xdbl4, *ptot, *hend, *hstart;
    __half *xzh, *xh, *winT, *woutT, *yh;
    bf16 *xch, *xcl, *wxh, *wxl;
    cudaGetSymbolAddress((void**)&xzh,   g_xzh);
    cudaGetSymbolAddress((void**)&coefp, g_coef);
    cudaGetSymbolAddress((void**)&xdbl4, g_xdbl4);
    cudaGetSymbolAddress((void**)&ptot,  g_ptot);
    cudaGetSymbolAddress((void**)&hend,  g_hend);
    cudaGetSymbolAddress((void**)&hstart,g_hstart);
    cudaGetSymbolAddress((void**)&xh,    g_xh);
    cudaGetSymbolAddress((void**)&winT,  g_winT);
    cudaGetSymbolAddress((void**)&woutT, g_woutT);
    cudaGetSymbolAddress((void**)&xch,   g_xch);
    cudaGetSymbolAddress((void**)&xcl,   g_xcl);
    cudaGetSymbolAddress((void**)&wxh,   g_wxT_h);
    cudaGetSymbolAddress((void**)&wxl,   g_wxT_l);
    cudaGetSymbolAddress((void**)&yh,    g_yh);

    const int SMEM1 = 3 * (2*128*PITCH);         // 110592
    const int SMEMW = 3 * (4*64*WPITCH);         // 61440
    cudaFuncSetAttribute((const void*)gemm_f16<__half>, cudaFuncAttributeMaxDynamicSharedMemorySize, SMEM1);
    cudaFuncSetAttribute((const void*)gemm_f16<float>,  cudaFuncAttributeMaxDynamicSharedMemorySize, SMEM1);
    cudaFuncSetAttribute((const void*)gemm_wx64,        cudaFuncAttributeMaxDynamicSharedMemorySize, SMEMW);

    // 1) fused operand prep (vectorized convert + transposes + wx split)
    prep_fused<<<8192 + 4096 + 2048 + 128, dim3(32,8)>>>(
        x, xh, W_in, winT, W_out, woutT, W_x, wxh, wxl);
    // 2) GEMM1: xz(fp16) = x @ W_in
    gemm_f16<__half><<<dim3(4096/128, 8192/128), 256, SMEM1>>>(
        (const u16*)xh, (const u16*)winT, xzh, 4096, 1024);
    // 3) conv + silu (2-wide)
    conv_silu_tiled<<<dim3(DINNER/512, LL/CONV_TL, BB), 256>>>(
        xzh, conv_w, conv_b, xch, xcl);
    // 4) x_dbl partials = xc @ W_x  (split-K x4)
    gemm_wx64<<<dim3(KSPLIT, 8192/64), 256, SMEMW>>>(
        (const u16*)xch, (const u16*)xcl, (const u16*)wxh, (const u16*)wxl, xdbl4, 64, 2048);
    // 5) MERGED coef + chunk products + scan pass 1
    scan_pass1_coef<<<dim3(DINNER/512, NCH, BB), 256>>>(
        xdbl4, A_log, coefp, ptot, xch, xcl, hend);
    // 6) scan pass 2
    scan_pass2<<<(BB*DINNER*DSTATE)/256, 256>>>(hend, ptot, hstart);
    // 7) scan pass 3
    scan_pass3<<<dim3(DINNER/512, NCH, BB), 256>>>(coefp, hstart, xch, xcl, xzh, D_param, yh);
    // 8) out = y @ W_out
    gemm_f16<float><<<dim3(1024/128, 8192/128), 256, SMEM1>>>(
        (const u16*)yh, (const u16*)woutT, out, 1024, 2048);
}